// round 14
// baseline (speedup 1.0000x reference)
#include <cuda_runtime.h>
#include <cuda_fp16.h>
#include <cstdint>

#define NN 50000
#define EE 400000
#define DD 512
#define EPS 1e-5f

// -------- scratch (static __device__; no cudaMalloc allowed) ----------------
__device__ __half g_ag[(size_t)NN * DD];   // mean-aggregated, fp16
__device__ __half g_xhi[(size_t)NN * DD];  // x, fp16
__device__ __half g_whi[512 * 1024];       // [n][k] k<512:Wl, k>=512:Wr
__device__ int   g_cnt[NN];
__device__ int   g_off[NN + 1];
__device__ int   g_woff[NN];
__device__ int   g_eidx[EE];
__device__ float g_colsum[DD];
__device__ float g_colsumsq[DD];

// -------- helpers ------------------------------------------------------------
__device__ __forceinline__ uint32_t smem_u32(const void* p) {
    uint32_t a;
    asm("{ .reg .u64 t; cvta.to.shared.u64 t, %1; cvt.u32.u64 %0, t; }"
        : "=r"(a) : "l"(p));
    return a;
}

#define LDSM4(r0, r1, r2, r3, addr) \
    asm volatile("ldmatrix.sync.aligned.m8n8.x4.shared.b16 {%0,%1,%2,%3}, [%4];" \
        : "=r"(r0), "=r"(r1), "=r"(r2), "=r"(r3) : "r"(addr))

#define MMA_F16(d, a, b0, b1) \
    asm volatile("mma.sync.aligned.m16n8k16.row.col.f32.f16.f16.f32 " \
        "{%0,%1,%2,%3}, {%4,%5,%6,%7}, {%8,%9}, {%0,%1,%2,%3};" \
        : "+f"((d)[0]), "+f"((d)[1]), "+f"((d)[2]), "+f"((d)[3]) \
        : "r"((a)[0]), "r"((a)[1]), "r"((a)[2]), "r"((a)[3]), "r"(b0), "r"(b1))

#define CP16(dst, src, nb) \
    asm volatile("cp.async.cg.shared.global [%0], [%1], 16, %2;" \
        :: "r"(dst), "l"(src), "r"(nb))
#define CP_COMMIT() asm volatile("cp.async.commit_group;" ::: "memory")
#define CP_WAIT1()  asm volatile("cp.async.wait_group 1;" ::: "memory")
#define CP_WAIT0()  asm volatile("cp.async.wait_group 0;" ::: "memory")

// tile config (R8 proven-best): 128x128 CTA tile, 8 warps (4x2) of 32x64
#define BM 128
#define BN 128
#define STAGE_B 20480      // {A,B} x 128 rows x 80 B
#define SMEM_BYTES (3 * STAGE_B)

// ======================= pre-conversion kernels ==============================
__global__ __launch_bounds__(256) void conv_w(
    const float* __restrict__ Wl, const float* __restrict__ Wr)
{
    int i = blockIdx.x * blockDim.x + threadIdx.x;
    if (i >= 512 * 1024) return;
    int n = i >> 10, k = i & 1023;
    float v = (k < 512) ? Wl[n * 512 + k] : Wr[n * 512 + (k - 512)];
    g_whi[i] = __float2half_rn(v);
}

__global__ __launch_bounds__(256) void conv_x(const float* __restrict__ x, int N) {
    size_t i = (size_t)blockIdx.x * blockDim.x + threadIdx.x;
    size_t tot = (size_t)N * DD / 4;
    if (i >= tot) return;
    float4 v = ((const float4*)x)[i];
    __half2 hi0(__float2half_rn(v.x), __float2half_rn(v.y));
    __half2 hi1(__float2half_rn(v.z), __float2half_rn(v.w));
    ((__half2*)g_xhi)[i * 2] = hi0;
    ((__half2*)g_xhi)[i * 2 + 1] = hi1;
}

// ======================= CSR build + gather aggregation ======================
__global__ void zero_small() {
    int i = blockIdx.x * blockDim.x + threadIdx.x;
    if (i < NN) g_cnt[i] = 0;
    if (i < DD) { g_colsum[i] = 0.f; g_colsumsq[i] = 0.f; }
}

__global__ __launch_bounds__(256) void hist_kernel(const int* __restrict__ ei, int E) {
    int e = blockIdx.x * blockDim.x + threadIdx.x;
    if (e < E) atomicAdd(&g_cnt[__ldg(&ei[E + e])], 1);
}

__global__ __launch_bounds__(1024) void scan_kernel() {
    __shared__ int tsum[1024];
    const int CH = (NN + 1023) / 1024;
    int t = threadIdx.x;
    int beg = t * CH, end = min(beg + CH, NN);
    int s = 0;
    for (int i = beg; i < end; ++i) s += g_cnt[i];
    tsum[t] = s;
    __syncthreads();
    for (int d = 1; d < 1024; d <<= 1) {
        int v = (t >= d) ? tsum[t - d] : 0;
        __syncthreads();
        tsum[t] += v;
        __syncthreads();
    }
    int excl = (t == 0) ? 0 : tsum[t - 1];
    for (int i = beg; i < end; ++i) {
        int c = g_cnt[i];
        g_off[i] = excl;
        g_woff[i] = excl;
        excl += c;
    }
    if (t == 1023) g_off[NN] = tsum[1023];
}

__global__ __launch_bounds__(256) void fill_kernel(const int* __restrict__ ei, int E) {
    int e = blockIdx.x * blockDim.x + threadIdx.x;
    if (e >= E) return;
    int src = __ldg(&ei[e]);
    int dst = __ldg(&ei[E + e]);
    int pos = atomicAdd(&g_woff[dst], 1);
    g_eidx[pos] = src;
}

// gather-reduce over fp16 x: one warp per node; fp32 accum; fp16 mean out.
__global__ __launch_bounds__(256) void gather_kernel(int N) {
    int warp = (blockIdx.x * blockDim.x + threadIdx.x) >> 5;
    if (warp >= N) return;
    int lane = threadIdx.x & 31;
    int beg = g_off[warp], end = g_off[warp + 1];

    float acc[16];
#pragma unroll
    for (int i = 0; i < 16; ++i) acc[i] = 0.f;

    auto addrow = [&](uint4 p0, uint4 p1) {
        const __half2* h0 = (const __half2*)&p0;
        const __half2* h1 = (const __half2*)&p1;
#pragma unroll
        for (int j = 0; j < 4; ++j) {
            float2 a = __half22float2(h0[j]);
            acc[j * 2] += a.x; acc[j * 2 + 1] += a.y;
            float2 c = __half22float2(h1[j]);
            acc[8 + j * 2] += c.x; acc[8 + j * 2 + 1] += c.y;
        }
    };

    int e = beg;
    for (; e + 4 <= end; e += 4) {
        int s0 = __ldg(&g_eidx[e]);
        int s1 = __ldg(&g_eidx[e + 1]);
        int s2 = __ldg(&g_eidx[e + 2]);
        int s3 = __ldg(&g_eidx[e + 3]);
        const uint4* r0 = (const uint4*)&g_xhi[(size_t)s0 * DD + lane * 16];
        const uint4* r1 = (const uint4*)&g_xhi[(size_t)s1 * DD + lane * 16];
        const uint4* r2 = (const uint4*)&g_xhi[(size_t)s2 * DD + lane * 16];
        const uint4* r3 = (const uint4*)&g_xhi[(size_t)s3 * DD + lane * 16];
        uint4 a0 = r0[0], a1 = r0[1];
        uint4 b0 = r1[0], b1 = r1[1];
        uint4 c0 = r2[0], c1 = r2[1];
        uint4 d0 = r3[0], d1 = r3[1];
        addrow(a0, a1); addrow(b0, b1); addrow(c0, c1); addrow(d0, d1);
    }
    for (; e < end; ++e) {
        int s0 = __ldg(&g_eidx[e]);
        const uint4* r0 = (const uint4*)&g_xhi[(size_t)s0 * DD + lane * 16];
        uint4 a0 = r0[0], a1 = r0[1];
        addrow(a0, a1);
    }

    float inv = 1.0f / (float)max(end - beg, 1);
    uint4 o0, o1;
    __half2* ho0 = (__half2*)&o0;
    __half2* ho1 = (__half2*)&o1;
#pragma unroll
    for (int j = 0; j < 4; ++j) {
        ho0[j] = __floats2half2_rn(acc[j * 2] * inv, acc[j * 2 + 1] * inv);
        ho1[j] = __floats2half2_rn(acc[8 + j * 2] * inv, acc[8 + j * 2 + 1] * inv);
    }
    uint4* dst = (uint4*)&g_ag[(size_t)warp * DD + lane * 16];
    dst[0] = o0; dst[1] = o1;
}

// ======================= split fp16 tensor GEMMs (3-stage cp.async) ==========
// PHASE 0: out = x @ Wr^T + bl  (full-grid launch: CTA turnover lets gather
//          interleave on the same SMs)
// PHASE 1: out += ag @ Wl^T, fused colstats (persistent grid: no wave tail)
template <int PHASE>
__global__ __launch_bounds__(256, 2) void gemm_half(
    const float* __restrict__ bl, float* __restrict__ out, int N, int tiles)
{
    extern __shared__ char sm[];
    const uint32_t s0 = smem_u32(sm);
    const int tid = threadIdx.x;
    const int lane = tid & 31, wid = tid >> 5;
    const int warp_m = (wid >> 1) * 32;
    const int warp_n = (wid & 1) * 64;

    const __half* Ah = PHASE ? g_ag : g_xhi;
    const int wkoff = PHASE ? 0 : 512;     // Wl at k<512, Wr at k>=512

    int row0, col0;

    auto issue_chunk = [&](int kt, int s) {
        const uint32_t sb = s0 + s * STAGE_B;
        const int kk = kt * 32;
#pragma unroll
        for (int it = 0; it < 2; ++it) {
            int idx = it * 256 + tid;            // 0..511
            int r = idx >> 2, c16 = idx & 3;
            int rg = row0 + r;
            int nb = (rg < N) ? 16 : 0;
            int rc = min(rg, N - 1);
            const __half* sH = Ah + (size_t)rc * DD + kk + c16 * 8;
            uint32_t d = sb + (uint32_t)r * 80 + c16 * 16;
            CP16(d, sH, nb);
        }
#pragma unroll
        for (int it = 0; it < 2; ++it) {
            int idx = it * 256 + tid;
            int r = idx >> 2, c16 = idx & 3;
            const __half* sH = g_whi + (size_t)(col0 + r) * 1024 + wkoff + kk + c16 * 8;
            uint32_t d = sb + 10240 + (uint32_t)r * 80 + c16 * 16;
            CP16(d, sH, 16);
        }
    };

    for (int t = blockIdx.x; t < tiles; t += gridDim.x) {
        __syncthreads();                     // protect stages from prior tile
        row0 = (t >> 2) * BM;
        col0 = (t & 3) * BN;

        float acc[2][8][4];
#pragma unroll
        for (int mf = 0; mf < 2; ++mf)
#pragma unroll
            for (int nf = 0; nf < 8; ++nf)
#pragma unroll
                for (int i = 0; i < 4; ++i) acc[mf][nf][i] = 0.f;

        issue_chunk(0, 0); CP_COMMIT();
        issue_chunk(1, 1); CP_COMMIT();

        int s = 0;               // stage of chunk kt
        for (int kt = 0; kt < 16; ++kt) {
            if (kt == 15) { CP_WAIT0(); } else { CP_WAIT1(); }
            __syncthreads();     // chunk kt visible; stage (kt+2)%3 free

            if (kt + 2 < 16) {
                int s2 = s + 2; if (s2 >= 3) s2 -= 3;
                issue_chunk(kt + 2, s2);
                CP_COMMIT();
            }

            const uint32_t ahiB = s0 + s * STAGE_B;
            const uint32_t bhiB = ahiB + 10240;
#pragma unroll
            for (int ks = 0; ks < 2; ++ks) {
                const uint32_t k0b = ks * 32;
                uint32_t ah[2][4];
                {
                    const int arow_l = (lane & 15);
                    const uint32_t acol = k0b + ((lane >> 4) << 4);
#pragma unroll
                    for (int mf = 0; mf < 2; ++mf) {
                        uint32_t off = (uint32_t)(warp_m + mf * 16 + arow_l) * 80 + acol;
                        LDSM4(ah[mf][0], ah[mf][1], ah[mf][2], ah[mf][3], ahiB + off);
                    }
                }
                const int brow_l = (lane & 7) + ((lane >> 4) << 3);
                const uint32_t bcol = k0b + (((lane >> 3) & 1) << 4);
#pragma unroll
                for (int pair = 0; pair < 4; ++pair) {
                    uint32_t boff = (uint32_t)(warp_n + pair * 16 + brow_l) * 80 + bcol;
                    uint32_t bh[4];
                    LDSM4(bh[0], bh[1], bh[2], bh[3], bhiB + boff);
#pragma unroll
                    for (int mf = 0; mf < 2; ++mf)
#pragma unroll
                        for (int nfl = 0; nfl < 2; ++nfl) {
                            int nf = pair * 2 + nfl;
                            MMA_F16(acc[mf][nf], ah[mf], bh[nfl * 2], bh[nfl * 2 + 1]);
                        }
                }
            }
            if (++s >= 3) s = 0;
        }

        // ---- epilogue ------------------------------------------------------
#pragma unroll
        for (int nf = 0; nf < 8; ++nf) {
            int c = col0 + warp_n + nf * 8 + 2 * (lane & 3);
            if (PHASE == 0) {
                float2 bb = *(const float2*)&bl[c];
#pragma unroll
                for (int mf = 0; mf < 2; ++mf) {
                    int m = row0 + warp_m + mf * 16 + (lane >> 2);
                    if (m < N)
                        *(float2*)&out[(size_t)m * DD + c] =
                            make_float2(acc[mf][nf][0] + bb.x, acc[mf][nf][1] + bb.y);
                    if (m + 8 < N)
                        *(float2*)&out[(size_t)(m + 8) * DD + c] =
                            make_float2(acc[mf][nf][2] + bb.x, acc[mf][nf][3] + bb.y);
                }
            } else {
                float sA = 0.f, sB = 0.f, qA = 0.f, qB = 0.f;
#pragma unroll
                for (int mf = 0; mf < 2; ++mf) {
                    int m = row0 + warp_m + mf * 16 + (lane >> 2);
                    if (m < N) {
                        float2 prev = *(const float2*)&out[(size_t)m * DD + c];
                        float o0 = acc[mf][nf][0] + prev.x, o1 = acc[mf][nf][1] + prev.y;
                        *(float2*)&out[(size_t)m * DD + c] = make_float2(o0, o1);
                        sA += o0; sB += o1; qA += o0 * o0; qB += o1 * o1;
                    }
                    if (m + 8 < N) {
                        float2 prev = *(const float2*)&out[(size_t)(m + 8) * DD + c];
                        float o0 = acc[mf][nf][2] + prev.x, o1 = acc[mf][nf][3] + prev.y;
                        *(float2*)&out[(size_t)(m + 8) * DD + c] = make_float2(o0, o1);
                        sA += o0; sB += o1; qA += o0 * o0; qB += o1 * o1;
                    }
                }
#pragma unroll
                for (int d = 4; d < 32; d <<= 1) {
                    sA += __shfl_xor_sync(0xffffffffu, sA, d);
                    sB += __shfl_xor_sync(0xffffffffu, sB, d);
                    qA += __shfl_xor_sync(0xffffffffu, qA, d);
                    qB += __shfl_xor_sync(0xffffffffu, qB, d);
                }
                if (lane < 4) {
                    atomicAdd(&g_colsum[c], sA);
                    atomicAdd(&g_colsum[c + 1], sB);
                    atomicAdd(&g_colsumsq[c], qA);
                    atomicAdd(&g_colsumsq[c + 1], qB);
                }
            }
        }
    }
}

// ======================= fused stats + BN + relu + residual ==================
// persistent grid; each CTA derives mu/rstd from colsum/colsumsq in smem,
// caches gamma/beta, then streams its share of rows. residual from fp16 g_xhi.
__global__ __launch_bounds__(256) void final_kernel(
    const float* __restrict__ gamma, const float* __restrict__ beta,
    float* __restrict__ out, int N)
{
    __shared__ float smu[DD], srs[DD], sga[DD], sbe[DD];
    int tid = threadIdx.x;
    float invn = 1.0f / (float)N;
    for (int c = tid; c < DD; c += 256) {
        float mu = g_colsum[c] * invn;
        float var = g_colsumsq[c] * invn - mu * mu;
        smu[c] = mu;
        srs[c] = rsqrtf(var + EPS);
        sga[c] = gamma[c];
        sbe[c] = beta[c];
    }
    __syncthreads();

    size_t total4 = (size_t)N * DD / 4;
    size_t stride = (size_t)gridDim.x * 256;
    for (size_t idx = (size_t)blockIdx.x * 256 + tid; idx < total4; idx += stride) {
        int c = (int)((idx * 4) & (DD - 1));
        float4 h = ((float4*)out)[idx];
        uint2 xp = ((const uint2*)g_xhi)[idx];
        float2 xv0 = __half22float2(*(const __half2*)&xp.x);
        float2 xv1 = __half22float2(*(const __half2*)&xp.y);
        float4 o;
        o.x = fmaxf(fmaf((h.x - smu[c + 0]) * srs[c + 0], sga[c + 0], sbe[c + 0]), 0.f) + xv0.x;
        o.y = fmaxf(fmaf((h.y - smu[c + 1]) * srs[c + 1], sga[c + 1], sbe[c + 1]), 0.f) + xv0.y;
        o.z = fmaxf(fmaf((h.z - smu[c + 2]) * srs[c + 2], sga[c + 2], sbe[c + 2]), 0.f) + xv1.x;
        o.w = fmaxf(fmaf((h.w - smu[c + 3]) * srs[c + 3], sga[c + 3], sbe[c + 3]), 0.f) + xv1.y;
        ((float4*)out)[idx] = o;
    }
}

// ---------------------------------------------------------------------------
extern "C" void kernel_launch(void* const* d_in, const int* in_sizes, int n_in,
                              void* d_out, int out_size)
{
    const float* x  = (const float*)d_in[0];
    const int*   ei = (const int*)d_in[1];
    const float* Wl = (const float*)d_in[2];
    const float* bl = (const float*)d_in[3];
    const float* Wr = (const float*)d_in[4];
    const float* ga = (const float*)d_in[5];
    const float* be = (const float*)d_in[6];
    float* out = (float*)d_out;

    int N = in_sizes[0] / DD;
    int E = in_sizes[1] / 2;

    static cudaStream_t s2 = nullptr;
    static cudaEvent_t evFork = nullptr, evConv = nullptr, evGemmX = nullptr;
    static int npers = 0;
    static int once = 0;
    if (!once) {
        cudaStreamCreateWithFlags(&s2, cudaStreamNonBlocking);
        cudaEventCreateWithFlags(&evFork, cudaEventDisableTiming);
        cudaEventCreateWithFlags(&evConv, cudaEventDisableTiming);
        cudaEventCreateWithFlags(&evGemmX, cudaEventDisableTiming);
        cudaFuncSetAttribute(gemm_half<0>, cudaFuncAttributeMaxDynamicSharedMemorySize,
                             SMEM_BYTES);
        cudaFuncSetAttribute(gemm_half<1>, cudaFuncAttributeMaxDynamicSharedMemorySize,
                             SMEM_BYTES);
        int sms = 148;
        cudaDeviceGetAttribute(&sms, cudaDevAttrMultiProcessorCount, 0);
        npers = sms * 2;
        once = 1;
    }

    int tiles = (DD / BN) * ((N + BM - 1) / BM);
    size_t xtot4 = (size_t)N * DD / 4;

    // fork: conversions + gemm_x on s2; CSR build on main
    cudaEventRecord(evFork, 0);
    cudaStreamWaitEvent(s2, evFork, 0);

    conv_x<<<(int)((xtot4 + 255) / 256), 256, 0, s2>>>(x, N);
    conv_w<<<(512 * 1024 + 255) / 256, 256, 0, s2>>>(Wl, Wr);
    cudaEventRecord(evConv, s2);
    gemm_half<0><<<tiles, 256, SMEM_BYTES, s2>>>(bl, out, N, tiles); // x@Wr^T+bl
    cudaEventRecord(evGemmX, s2);

    zero_small<<<(NN + 255) / 256, 256>>>();
    hist_kernel<<<(E + 255) / 256, 256>>>(ei, E);
    scan_kernel<<<1, 1024>>>();
    fill_kernel<<<(E + 255) / 256, 256>>>(ei, E);

    cudaStreamWaitEvent(0, evConv, 0);           // gather reads g_xhi
    gather_kernel<<<(N + 7) / 8, 256>>>(N);

    cudaStreamWaitEvent(0, evGemmX, 0);          // out must hold x@Wr before +=
    int g1 = npers < tiles ? npers : tiles;
    gemm_half<1><<<g1, 256, SMEM_BYTES>>>(bl, out, N, tiles);       // += ag@Wl^T

    final_kernel<<<npers, 256>>>(ga, be, out, N);
}

// round 15
// speedup vs baseline: 1.1275x; 1.1275x over previous
#include <cuda_runtime.h>
#include <cuda_fp16.h>
#include <cstdint>

#define NN 50000
#define EE 400000
#define DD 512
#define EPS 1e-5f

// -------- scratch (static __device__; no cudaMalloc allowed) ----------------
__device__ __half g_ag[(size_t)NN * DD];   // mean-aggregated, fp16
__device__ __half g_xhi[(size_t)NN * DD];  // x, fp16
__device__ __half g_h1[(size_t)NN * DD];   // phase-0 partial (x@Wr^T + b), fp16
__device__ __half g_whi[512 * 1024];       // [n][k] k<512:Wl, k>=512:Wr
__device__ int   g_cnt[NN];
__device__ int   g_off[NN + 1];
__device__ int   g_woff[NN];
__device__ int   g_eidx[EE];
__device__ float g_colsum[DD];
__device__ float g_colsumsq[DD];
__device__ float g_mu[DD];
__device__ float g_rstd[DD];

// -------- helpers ------------------------------------------------------------
__device__ __forceinline__ uint32_t smem_u32(const void* p) {
    uint32_t a;
    asm("{ .reg .u64 t; cvta.to.shared.u64 t, %1; cvt.u32.u64 %0, t; }"
        : "=r"(a) : "l"(p));
    return a;
}

#define LDSM4(r0, r1, r2, r3, addr) \
    asm volatile("ldmatrix.sync.aligned.m8n8.x4.shared.b16 {%0,%1,%2,%3}, [%4];" \
        : "=r"(r0), "=r"(r1), "=r"(r2), "=r"(r3) : "r"(addr))

#define MMA_F16(d, a, b0, b1) \
    asm volatile("mma.sync.aligned.m16n8k16.row.col.f32.f16.f16.f32 " \
        "{%0,%1,%2,%3}, {%4,%5,%6,%7}, {%8,%9}, {%0,%1,%2,%3};" \
        : "+f"((d)[0]), "+f"((d)[1]), "+f"((d)[2]), "+f"((d)[3]) \
        : "r"((a)[0]), "r"((a)[1]), "r"((a)[2]), "r"((a)[3]), "r"(b0), "r"(b1))

#define CP16(dst, src, nb) \
    asm volatile("cp.async.cg.shared.global [%0], [%1], 16, %2;" \
        :: "r"(dst), "l"(src), "r"(nb))
#define CP_COMMIT() asm volatile("cp.async.commit_group;" ::: "memory")
#define CP_WAIT1()  asm volatile("cp.async.wait_group 1;" ::: "memory")
#define CP_WAIT0()  asm volatile("cp.async.wait_group 0;" ::: "memory")

// tile config (R8 proven-best): 128x128 CTA tile, 8 warps (4x2) of 32x64
#define BM 128
#define BN 128
#define STAGE_B 20480      // {A,B} x 128 rows x 80 B
#define SMEM_BYTES (3 * STAGE_B)

// ======================= pre-conversion kernels ==============================
__global__ __launch_bounds__(256) void conv_w(
    const float* __restrict__ Wl, const float* __restrict__ Wr)
{
    int i = blockIdx.x * blockDim.x + threadIdx.x;
    if (i >= 512 * 1024) return;
    int n = i >> 10, k = i & 1023;
    float v = (k < 512) ? Wl[n * 512 + k] : Wr[n * 512 + (k - 512)];
    g_whi[i] = __float2half_rn(v);
}

__global__ __launch_bounds__(256) void conv_x(const float* __restrict__ x, int N) {
    size_t i = (size_t)blockIdx.x * blockDim.x + threadIdx.x;
    size_t tot = (size_t)N * DD / 4;
    if (i >= tot) return;
    float4 v = ((const float4*)x)[i];
    __half2 hi0(__float2half_rn(v.x), __float2half_rn(v.y));
    __half2 hi1(__float2half_rn(v.z), __float2half_rn(v.w));
    ((__half2*)g_xhi)[i * 2] = hi0;
    ((__half2*)g_xhi)[i * 2 + 1] = hi1;
}

// ======================= CSR build + gather aggregation ======================
__global__ void zero_small() {
    int i = blockIdx.x * blockDim.x + threadIdx.x;
    if (i < NN) g_cnt[i] = 0;
    if (i < DD) { g_colsum[i] = 0.f; g_colsumsq[i] = 0.f; }
}

__global__ __launch_bounds__(256) void hist_kernel(const int* __restrict__ ei, int E) {
    int e = blockIdx.x * blockDim.x + threadIdx.x;
    if (e < E) atomicAdd(&g_cnt[__ldg(&ei[E + e])], 1);
}

__global__ __launch_bounds__(1024) void scan_kernel() {
    __shared__ int tsum[1024];
    const int CH = (NN + 1023) / 1024;
    int t = threadIdx.x;
    int beg = t * CH, end = min(beg + CH, NN);
    int s = 0;
    for (int i = beg; i < end; ++i) s += g_cnt[i];
    tsum[t] = s;
    __syncthreads();
    for (int d = 1; d < 1024; d <<= 1) {
        int v = (t >= d) ? tsum[t - d] : 0;
        __syncthreads();
        tsum[t] += v;
        __syncthreads();
    }
    int excl = (t == 0) ? 0 : tsum[t - 1];
    for (int i = beg; i < end; ++i) {
        int c = g_cnt[i];
        g_off[i] = excl;
        g_woff[i] = excl;
        excl += c;
    }
    if (t == 1023) g_off[NN] = tsum[1023];
}

__global__ __launch_bounds__(256) void fill_kernel(const int* __restrict__ ei, int E) {
    int e = blockIdx.x * blockDim.x + threadIdx.x;
    if (e >= E) return;
    int src = __ldg(&ei[e]);
    int dst = __ldg(&ei[E + e]);
    int pos = atomicAdd(&g_woff[dst], 1);
    g_eidx[pos] = src;
}

// gather-reduce over fp16 x: one warp per node; fp32 accum; fp16 mean out.
__global__ __launch_bounds__(256) void gather_kernel(int N) {
    int warp = (blockIdx.x * blockDim.x + threadIdx.x) >> 5;
    if (warp >= N) return;
    int lane = threadIdx.x & 31;
    int beg = g_off[warp], end = g_off[warp + 1];

    float acc[16];
#pragma unroll
    for (int i = 0; i < 16; ++i) acc[i] = 0.f;

    auto addrow = [&](uint4 p0, uint4 p1) {
        const __half2* h0 = (const __half2*)&p0;
        const __half2* h1 = (const __half2*)&p1;
#pragma unroll
        for (int j = 0; j < 4; ++j) {
            float2 a = __half22float2(h0[j]);
            acc[j * 2] += a.x; acc[j * 2 + 1] += a.y;
            float2 c = __half22float2(h1[j]);
            acc[8 + j * 2] += c.x; acc[8 + j * 2 + 1] += c.y;
        }
    };

    int e = beg;
    for (; e + 4 <= end; e += 4) {
        int s0 = __ldg(&g_eidx[e]);
        int s1 = __ldg(&g_eidx[e + 1]);
        int s2 = __ldg(&g_eidx[e + 2]);
        int s3 = __ldg(&g_eidx[e + 3]);
        const uint4* r0 = (const uint4*)&g_xhi[(size_t)s0 * DD + lane * 16];
        const uint4* r1 = (const uint4*)&g_xhi[(size_t)s1 * DD + lane * 16];
        const uint4* r2 = (const uint4*)&g_xhi[(size_t)s2 * DD + lane * 16];
        const uint4* r3 = (const uint4*)&g_xhi[(size_t)s3 * DD + lane * 16];
        uint4 a0 = r0[0], a1 = r0[1];
        uint4 b0 = r1[0], b1 = r1[1];
        uint4 c0 = r2[0], c1 = r2[1];
        uint4 d0 = r3[0], d1 = r3[1];
        addrow(a0, a1); addrow(b0, b1); addrow(c0, c1); addrow(d0, d1);
    }
    for (; e < end; ++e) {
        int s0 = __ldg(&g_eidx[e]);
        const uint4* r0 = (const uint4*)&g_xhi[(size_t)s0 * DD + lane * 16];
        uint4 a0 = r0[0], a1 = r0[1];
        addrow(a0, a1);
    }

    float inv = 1.0f / (float)max(end - beg, 1);
    uint4 o0, o1;
    __half2* ho0 = (__half2*)&o0;
    __half2* ho1 = (__half2*)&o1;
#pragma unroll
    for (int j = 0; j < 4; ++j) {
        ho0[j] = __floats2half2_rn(acc[j * 2] * inv, acc[j * 2 + 1] * inv);
        ho1[j] = __floats2half2_rn(acc[8 + j * 2] * inv, acc[8 + j * 2 + 1] * inv);
    }
    uint4* dst = (uint4*)&g_ag[(size_t)warp * DD + lane * 16];
    dst[0] = o0; dst[1] = o1;
}

// ======================= split fp16 tensor GEMMs (3-stage cp.async) ==========
// PHASE 0: g_h1 = fp16(x @ Wr^T + bl)   (full-grid; overlaps CSR+gather)
// PHASE 1: out = g_h1 + ag @ Wl^T, fused colstats (persistent grid)
template <int PHASE>
__global__ __launch_bounds__(256, 2) void gemm_half(
    const float* __restrict__ bl, float* __restrict__ out, int N, int tiles)
{
    extern __shared__ char sm[];
    const uint32_t s0 = smem_u32(sm);
    const int tid = threadIdx.x;
    const int lane = tid & 31, wid = tid >> 5;
    const int warp_m = (wid >> 1) * 32;
    const int warp_n = (wid & 1) * 64;

    const __half* Ah = PHASE ? g_ag : g_xhi;
    const int wkoff = PHASE ? 0 : 512;     // Wl at k<512, Wr at k>=512

    int row0, col0;

    auto issue_chunk = [&](int kt, int s) {
        const uint32_t sb = s0 + s * STAGE_B;
        const int kk = kt * 32;
#pragma unroll
        for (int it = 0; it < 2; ++it) {
            int idx = it * 256 + tid;            // 0..511
            int r = idx >> 2, c16 = idx & 3;
            int rg = row0 + r;
            int nb = (rg < N) ? 16 : 0;
            int rc = min(rg, N - 1);
            const __half* sH = Ah + (size_t)rc * DD + kk + c16 * 8;
            uint32_t d = sb + (uint32_t)r * 80 + c16 * 16;
            CP16(d, sH, nb);
        }
#pragma unroll
        for (int it = 0; it < 2; ++it) {
            int idx = it * 256 + tid;
            int r = idx >> 2, c16 = idx & 3;
            const __half* sH = g_whi + (size_t)(col0 + r) * 1024 + wkoff + kk + c16 * 8;
            uint32_t d = sb + 10240 + (uint32_t)r * 80 + c16 * 16;
            CP16(d, sH, 16);
        }
    };

    for (int t = blockIdx.x; t < tiles; t += gridDim.x) {
        __syncthreads();                     // protect stages from prior tile
        row0 = (t >> 2) * BM;
        col0 = (t & 3) * BN;

        float acc[2][8][4];
#pragma unroll
        for (int mf = 0; mf < 2; ++mf)
#pragma unroll
            for (int nf = 0; nf < 8; ++nf)
#pragma unroll
                for (int i = 0; i < 4; ++i) acc[mf][nf][i] = 0.f;

        issue_chunk(0, 0); CP_COMMIT();
        issue_chunk(1, 1); CP_COMMIT();

        int s = 0;               // stage of chunk kt
        for (int kt = 0; kt < 16; ++kt) {
            if (kt == 15) { CP_WAIT0(); } else { CP_WAIT1(); }
            __syncthreads();     // chunk kt visible; stage (kt+2)%3 free

            if (kt + 2 < 16) {
                int s2 = s + 2; if (s2 >= 3) s2 -= 3;
                issue_chunk(kt + 2, s2);
                CP_COMMIT();
            }

            const uint32_t ahiB = s0 + s * STAGE_B;
            const uint32_t bhiB = ahiB + 10240;
#pragma unroll
            for (int ks = 0; ks < 2; ++ks) {
                const uint32_t k0b = ks * 32;
                uint32_t ah[2][4];
                {
                    const int arow_l = (lane & 15);
                    const uint32_t acol = k0b + ((lane >> 4) << 4);
#pragma unroll
                    for (int mf = 0; mf < 2; ++mf) {
                        uint32_t off = (uint32_t)(warp_m + mf * 16 + arow_l) * 80 + acol;
                        LDSM4(ah[mf][0], ah[mf][1], ah[mf][2], ah[mf][3], ahiB + off);
                    }
                }
                const int brow_l = (lane & 7) + ((lane >> 4) << 3);
                const uint32_t bcol = k0b + (((lane >> 3) & 1) << 4);
#pragma unroll
                for (int pair = 0; pair < 4; ++pair) {
                    uint32_t boff = (uint32_t)(warp_n + pair * 16 + brow_l) * 80 + bcol;
                    uint32_t bh[4];
                    LDSM4(bh[0], bh[1], bh[2], bh[3], bhiB + boff);
#pragma unroll
                    for (int mf = 0; mf < 2; ++mf)
#pragma unroll
                        for (int nfl = 0; nfl < 2; ++nfl) {
                            int nf = pair * 2 + nfl;
                            MMA_F16(acc[mf][nf], ah[mf], bh[nfl * 2], bh[nfl * 2 + 1]);
                        }
                }
            }
            if (++s >= 3) s = 0;
        }

        // ---- epilogue ------------------------------------------------------
#pragma unroll
        for (int nf = 0; nf < 8; ++nf) {
            int c = col0 + warp_n + nf * 8 + 2 * (lane & 3);
            if (PHASE == 0) {
                float2 bb = *(const float2*)&bl[c];
#pragma unroll
                for (int mf = 0; mf < 2; ++mf) {
                    int m = row0 + warp_m + mf * 16 + (lane >> 2);
                    if (m < N)
                        *(__half2*)&g_h1[(size_t)m * DD + c] =
                            __floats2half2_rn(acc[mf][nf][0] + bb.x,
                                              acc[mf][nf][1] + bb.y);
                    if (m + 8 < N)
                        *(__half2*)&g_h1[(size_t)(m + 8) * DD + c] =
                            __floats2half2_rn(acc[mf][nf][2] + bb.x,
                                              acc[mf][nf][3] + bb.y);
                }
            } else {
                float sA = 0.f, sB = 0.f, qA = 0.f, qB = 0.f;
#pragma unroll
                for (int mf = 0; mf < 2; ++mf) {
                    int m = row0 + warp_m + mf * 16 + (lane >> 2);
                    if (m < N) {
                        float2 prev = __half22float2(
                            *(const __half2*)&g_h1[(size_t)m * DD + c]);
                        float o0 = acc[mf][nf][0] + prev.x, o1 = acc[mf][nf][1] + prev.y;
                        *(float2*)&out[(size_t)m * DD + c] = make_float2(o0, o1);
                        sA += o0; sB += o1; qA += o0 * o0; qB += o1 * o1;
                    }
                    if (m + 8 < N) {
                        float2 prev = __half22float2(
                            *(const __half2*)&g_h1[(size_t)(m + 8) * DD + c]);
                        float o0 = acc[mf][nf][2] + prev.x, o1 = acc[mf][nf][3] + prev.y;
                        *(float2*)&out[(size_t)(m + 8) * DD + c] = make_float2(o0, o1);
                        sA += o0; sB += o1; qA += o0 * o0; qB += o1 * o1;
                    }
                }
#pragma unroll
                for (int d = 4; d < 32; d <<= 1) {
                    sA += __shfl_xor_sync(0xffffffffu, sA, d);
                    sB += __shfl_xor_sync(0xffffffffu, sB, d);
                    qA += __shfl_xor_sync(0xffffffffu, qA, d);
                    qB += __shfl_xor_sync(0xffffffffu, qB, d);
                }
                if (lane < 4) {
                    atomicAdd(&g_colsum[c], sA);
                    atomicAdd(&g_colsum[c + 1], sB);
                    atomicAdd(&g_colsumsq[c], qA);
                    atomicAdd(&g_colsumsq[c + 1], qB);
                }
            }
        }
    }
}

// ======================= BN stats + epilogue =================================
__global__ void stats_kernel(int N) {
    int c = threadIdx.x;
    float invn = 1.0f / (float)N;
    float mu = g_colsum[c] * invn;
    float var = g_colsumsq[c] * invn - mu * mu;
    g_mu[c] = mu;
    g_rstd[c] = rsqrtf(var + EPS);
}

// residual read from fp16 g_xhi
__global__ __launch_bounds__(256) void final_kernel(
    const float* __restrict__ gamma, const float* __restrict__ beta,
    float* __restrict__ out, int N)
{
    size_t idx = (size_t)blockIdx.x * blockDim.x + threadIdx.x;
    size_t total4 = (size_t)N * DD / 4;
    if (idx >= total4) return;
    int c = (int)((idx * 4) & (DD - 1));
    float4 h  = ((float4*)out)[idx];
    uint2 xp = ((const uint2*)g_xhi)[idx];
    float2 xv0 = __half22float2(*(const __half2*)&xp.x);
    float2 xv1 = __half22float2(*(const __half2*)&xp.y);
    float4 mu = *(const float4*)&g_mu[c];
    float4 rs = *(const float4*)&g_rstd[c];
    float4 ga = *(const float4*)&gamma[c];
    float4 be = *(const float4*)&beta[c];
    float4 o;
    o.x = fmaxf(fmaf((h.x - mu.x) * rs.x, ga.x, be.x), 0.f) + xv0.x;
    o.y = fmaxf(fmaf((h.y - mu.y) * rs.y, ga.y, be.y), 0.f) + xv0.y;
    o.z = fmaxf(fmaf((h.z - mu.z) * rs.z, ga.z, be.z), 0.f) + xv1.x;
    o.w = fmaxf(fmaf((h.w - mu.w) * rs.w, ga.w, be.w), 0.f) + xv1.y;
    ((float4*)out)[idx] = o;
}

// ---------------------------------------------------------------------------
extern "C" void kernel_launch(void* const* d_in, const int* in_sizes, int n_in,
                              void* d_out, int out_size)
{
    const float* x  = (const float*)d_in[0];
    const int*   ei = (const int*)d_in[1];
    const float* Wl = (const float*)d_in[2];
    const float* bl = (const float*)d_in[3];
    const float* Wr = (const float*)d_in[4];
    const float* ga = (const float*)d_in[5];
    const float* be = (const float*)d_in[6];
    float* out = (float*)d_out;

    int N = in_sizes[0] / DD;
    int E = in_sizes[1] / 2;

    static cudaStream_t s2 = nullptr;
    static cudaEvent_t evFork = nullptr, evConv = nullptr, evGemmX = nullptr;
    static int npers = 0;
    static int once = 0;
    if (!once) {
        cudaStreamCreateWithFlags(&s2, cudaStreamNonBlocking);
        cudaEventCreateWithFlags(&evFork, cudaEventDisableTiming);
        cudaEventCreateWithFlags(&evConv, cudaEventDisableTiming);
        cudaEventCreateWithFlags(&evGemmX, cudaEventDisableTiming);
        cudaFuncSetAttribute(gemm_half<0>, cudaFuncAttributeMaxDynamicSharedMemorySize,
                             SMEM_BYTES);
        cudaFuncSetAttribute(gemm_half<1>, cudaFuncAttributeMaxDynamicSharedMemorySize,
                             SMEM_BYTES);
        int sms = 148;
        cudaDeviceGetAttribute(&sms, cudaDevAttrMultiProcessorCount, 0);
        npers = sms * 2;
        once = 1;
    }

    int tiles = (DD / BN) * ((N + BM - 1) / BM);
    size_t xtot4 = (size_t)N * DD / 4;

    // fork: conversions + gemm_x on s2; CSR build on main
    cudaEventRecord(evFork, 0);
    cudaStreamWaitEvent(s2, evFork, 0);

    conv_x<<<(int)((xtot4 + 255) / 256), 256, 0, s2>>>(x, N);
    conv_w<<<(512 * 1024 + 255) / 256, 256, 0, s2>>>(Wl, Wr);
    cudaEventRecord(evConv, s2);
    gemm_half<0><<<tiles, 256, SMEM_BYTES, s2>>>(bl, out, N, tiles); // h1=x@Wr+b
    cudaEventRecord(evGemmX, s2);

    zero_small<<<(NN + 255) / 256, 256>>>();
    hist_kernel<<<(E + 255) / 256, 256>>>(ei, E);
    scan_kernel<<<1, 1024>>>();
    fill_kernel<<<(E + 255) / 256, 256>>>(ei, E);

    cudaStreamWaitEvent(0, evConv, 0);           // gather reads g_xhi
    gather_kernel<<<(N + 7) / 8, 256>>>(N);

    cudaStreamWaitEvent(0, evGemmX, 0);          // g_h1 ready before phase 1
    int g1 = npers < tiles ? npers : tiles;
    gemm_half<1><<<g1, 256, SMEM_BYTES>>>(bl, out, N, tiles);   // out=h1+ag@Wl

    stats_kernel<<<1, DD>>>(N);

    size_t tot4 = (size_t)N * DD / 4;
    final_kernel<<<(int)((tot4 + 255) / 256), 256>>>(ga, be, out, N);
}